// round 17
// baseline (speedup 1.0000x reference)
#include <cuda_runtime.h>
#include <cuda_bf16.h>
#include <cstdint>

#define NPTS 1024
#define HDIM 32
#define TCH 16
#define NCH (NPTS / TCH)        // 64 chunks

// dynamic smem (bytes):
//   xg ring [2][4 seq][TCH][100 f] : 0     .. 51200   (SEQB=6400, BUFB=25600)
//   s_h     [4 seq][2][32 f]       : 51200 .. 52224
#define SEQB 6400u
#define BUFB 25600u
#define HOFF 51200u
#define SMEM_TOT 52224

typedef unsigned long long u64;
typedef unsigned int u32;

// ---------- scratch ----------
__device__ float g_a[NPTS * HDIM];
__device__ float g_c[(NPTS + 8) * HDIM];
__device__ float g_h1[NPTS * HDIM];

// ---------- helpers ----------
__device__ __forceinline__ u64 f2fma(u64 a, u64 b, u64 c) {
    u64 d;
    asm("fma.rn.f32x2 %0, %1, %2, %3;" : "=l"(d) : "l"(a), "l"(b), "l"(c));
    return d;
}
__device__ __forceinline__ u64 add2(u64 a, u64 b) {
    u64 d;
    asm("add.rn.f32x2 %0, %1, %2;" : "=l"(d) : "l"(a), "l"(b));
    return d;
}
__device__ __forceinline__ u64 pack2(float lo, float hi) {
    u64 r;
    asm("mov.b64 %0, {%1, %2};" : "=l"(r) : "f"(lo), "f"(hi));
    return r;
}
__device__ __forceinline__ float hsum2(u64 v) {
    float lo, hi;
    asm("mov.b64 {%0, %1}, %2;" : "=f"(lo), "=f"(hi) : "l"(v));
    return lo + hi;
}
__device__ __forceinline__ float tanh_hw(float x) {
    float y;
    asm("tanh.approx.f32 %0, %1;" : "=f"(y) : "f"(x));
    return y;
}
__device__ __forceinline__ float sig_hw(float x) {
    return fmaf(tanh_hw(0.5f * x), 0.5f, 0.5f);
}
__device__ __forceinline__ u32 smem_u32(const void* p) {
    u32 a;
    asm("{ .reg .u64 t; cvta.to.shared.u64 t, %1; cvt.u32.u64 %0, t; }"
        : "=r"(a) : "l"(p));
    return a;
}
__device__ __forceinline__ void sts32(u32 addr, float v) {
    asm volatile("st.shared.b32 [%0], %1;" :: "r"(addr), "f"(v) : "memory");
}
__device__ __forceinline__ void sts64(u32 addr, u64 v) {
    asm volatile("st.shared.b64 [%0], %1;" :: "r"(addr), "l"(v) : "memory");
}
__device__ __forceinline__ float lds32f(u32 addr) {
    float v;
    asm volatile("ld.shared.b32 %0, [%1];" : "=f"(v) : "r"(addr));
    return v;
}
__device__ __forceinline__ void lds_v2(u64& p0, u64& p1, u32 addr) {
    asm volatile("ld.shared.v2.u64 {%0, %1}, [%2];"
                 : "=l"(p0), "=l"(p1) : "r"(addr));
}
__device__ __forceinline__ u32 tf32_of(float x) {
    u32 r;
    asm("cvt.rna.tf32.f32 %0, %1;" : "=r"(r) : "f"(x));
    return r;
}
__device__ __forceinline__ void mma_tf32(float& c0, float& c1, float& c2, float& c3,
                                         u32 a0, u32 a1, u32 a2, u32 a3,
                                         u32 b0, u32 b1) {
    asm("mma.sync.aligned.m16n8k8.row.col.f32.tf32.tf32.f32 "
        "{%0,%1,%2,%3}, {%4,%5,%6,%7}, {%8,%9}, {%0,%1,%2,%3};"
        : "+f"(c0), "+f"(c1), "+f"(c2), "+f"(c3)
        : "r"(a0), "r"(a1), "r"(a2), "r"(a3), "r"(b0), "r"(b1));
}
__device__ __forceinline__ void bar_all() {
    asm volatile("bar.sync 0;" ::: "memory");
}

// ---------- precompute: a_i = (Wa-Wb)@x_i + b ; c_j = Wb@x_j ----------
template <int F>
__global__ void __launch_bounds__(256)
pre_kernel(const float* __restrict__ x, const float* __restrict__ w,
           const float* __restrict__ b, float* __restrict__ a,
           float* __restrict__ c) {
    int wq = threadIdx.x >> 5;
    int l = threadIdx.x & 31;
    int i = blockIdx.x * 8 + wq;
    if (i >= NPTS) return;
    float av = b[l];
    float cv = 0.0f;
    const float* wr = w + l * (2 * F);
    const float* xr = x + i * F;
#pragma unroll
    for (int f = 0; f < F; ++f) {
        float xv = xr[f];
        float wa = wr[f];
        float wb = wr[F + f];
        av = fmaf(wa - wb, xv, av);
        cv = fmaf(wb, xv, cv);
    }
    a[i * HDIM + l] = av;
    c[i * HDIM + l] = cv;
}

// ---------- fused GRU: 1-seq consumers + 1-seq 16-step MMA producers ------
// 256 thr, 2 CTAs/SM: warps 0-3 consumers (seq = wid), warps 4-7 producers
// (seq = wid-4, A-tile rows = 16 time steps). 4 warps/SMSP for latency hiding.
template <int FUSE_CLF>
__global__ void __launch_bounds__(256, 2)
gru_fused_kernel(const float* __restrict__ a, const float* __restrict__ c,
                 const float* __restrict__ wih, const float* __restrict__ whh,
                 const float* __restrict__ bih, const float* __restrict__ bhh,
                 const float* __restrict__ clf_w, const float* __restrict__ clf_b,
                 float* __restrict__ out) {
    extern __shared__ __align__(16) char dsm[];
    const u32 xgb = smem_u32(dsm);

    const int wid = threadIdx.x >> 5;
    const int l = threadIdx.x & 31;

    if (wid < 4) {
        // ================= consumer (1 sequence) =================
        const int s = wid;
        const int i = blockIdx.x * 4 + s;

        u64 Whr[16], Whz[16], Whn[16];
        {
            const u64* pr = (const u64*)(whh + (0 * HDIM + l) * HDIM);
            const u64* pz = (const u64*)(whh + (1 * HDIM + l) * HDIM);
            const u64* pn = (const u64*)(whh + (2 * HDIM + l) * HDIM);
#pragma unroll
            for (int q = 0; q < 16; ++q) {
                Whr[q] = pr[q];
                Whz[q] = pz[q];
                Whn[q] = pn[q];
            }
        }
        const float b_r = bih[l] + bhh[l];
        const float b_z = bih[HDIM + l] + bhh[HDIM + l];
        const float b_xn = bih[2 * HDIM + l];
        const u64 init_n = pack2(bhh[2 * HDIM + l], 0.0f);  // b_hn

        const u32 hb = xgb + HOFF + (u32)s * 256u;
        const u32 xseq = xgb + (u32)s * SEQB;

        float h = 0.0f;

        for (int k = 0; k <= NCH; ++k) {
            if (k > 0) {
                const u32 xc = xseq + (u32)((k - 1) & 1) * BUFB + (u32)l * 4u;
#pragma unroll 4
                for (int t = 0; t < TCH; ++t) {
                    const u32 xo = xc + (u32)t * 400u;
                    const float xr = lds32f(xo);
                    const float xz = lds32f(xo + 128u);
                    const float xn = lds32f(xo + 256u);

                    const u32 po = hb + (u32)(t & 1) * 128u;
                    sts32(po + l * 4u, h);
                    __syncwarp();

                    u64 r0 = 0ULL, r1 = 0ULL, z0 = 0ULL, z1 = 0ULL;
                    u64 n0 = init_n, n1 = 0ULL;
#pragma unroll
                    for (int q = 0; q < 8; ++q) {
                        u64 p0, p1;
                        lds_v2(p0, p1, po + q * 16u);
                        r0 = f2fma(Whr[2 * q], p0, r0);
                        r1 = f2fma(Whr[2 * q + 1], p1, r1);
                        z0 = f2fma(Whz[2 * q], p0, z0);
                        z1 = f2fma(Whz[2 * q + 1], p1, z1);
                        n0 = f2fma(Whn[2 * q], p0, n0);
                        n1 = f2fma(Whn[2 * q + 1], p1, n1);
                    }
                    const float r = sig_hw(xr + b_r + hsum2(add2(r0, r1)));
                    const float z = sig_hw(xz + b_z + hsum2(add2(z0, z1)));
                    const float n = tanh_hw(fmaf(r, hsum2(add2(n0, n1)), xn + b_xn));
                    h = fmaf(z, h - n, n);
                }
            }
            bar_all();
        }

        if (FUSE_CLF) {
            sts32(hb + l * 4u, h);
            __syncwarp();
            if (l < 3) {
                float acc = clf_b[l];
                const float* cw = clf_w + l * HDIM;
#pragma unroll
                for (int hh = 0; hh < HDIM; ++hh)
                    acc = fmaf(cw[hh], lds32f(hb + (u32)hh * 4u), acc);
                out[i * 3 + l] = acc;
            }
        } else {
            out[i * HDIM + l] = h;
        }
    } else {
        // ================= producer (MMA, 1 seq x 16 steps) =================
        const int s = wid - 4;
        const int i = blockIdx.x * 4 + s;
        const int g = l >> 2, tig = l & 3;

        float av0[4], av1[4];
#pragma unroll
        for (int kc = 0; kc < 4; ++kc) {
            av0[kc] = a[i * HDIM + kc * 8 + tig];
            av1[kc] = a[i * HDIM + kc * 8 + tig + 4];
        }

        for (int k = 0; k <= NCH; ++k) {
            if (k < NCH) {
                const int j0 = k * TCH;
                const float* cr0 = c + (j0 + g) * HDIM;        // row = step g
                const float* cr1 = c + (j0 + g + 8) * HDIM;    // row = step g+8

                // u fragments (hi/lo) for this chunk, reused by both halves
                u32 UH[16], UL[16];
#pragma unroll
                for (int kc = 0; kc < 4; ++kc) {
                    const float u0 = fmaxf(av0[kc] + cr0[kc * 8 + tig], 0.0f);
                    const float u1 = fmaxf(av0[kc] + cr1[kc * 8 + tig], 0.0f);
                    const float u2 = fmaxf(av1[kc] + cr0[kc * 8 + tig + 4], 0.0f);
                    const float u3 = fmaxf(av1[kc] + cr1[kc * 8 + tig + 4], 0.0f);
                    UH[kc * 4 + 0] = tf32_of(u0);
                    UH[kc * 4 + 1] = tf32_of(u1);
                    UH[kc * 4 + 2] = tf32_of(u2);
                    UH[kc * 4 + 3] = tf32_of(u3);
                    UL[kc * 4 + 0] = tf32_of(u0 - __uint_as_float(UH[kc * 4 + 0]));
                    UL[kc * 4 + 1] = tf32_of(u1 - __uint_as_float(UH[kc * 4 + 1]));
                    UL[kc * 4 + 2] = tf32_of(u2 - __uint_as_float(UH[kc * 4 + 2]));
                    UL[kc * 4 + 3] = tf32_of(u3 - __uint_as_float(UH[kc * 4 + 3]));
                }

                const u32 base = xgb + (u32)(k & 1) * BUFB + (u32)s * SEQB
                               + (u32)g * 400u;
#pragma unroll
                for (int half = 0; half < 2; ++half) {
                    // reload Wih fragments for this half (L1-hot; producers have slack)
                    u32 XB[6][4][2];
#pragma unroll
                    for (int nn = 0; nn < 6; ++nn) {
                        const float* wr = wih + ((half * 6 + nn) * 8 + g) * HDIM;
#pragma unroll
                        for (int kc = 0; kc < 4; ++kc) {
                            XB[nn][kc][0] = tf32_of(wr[kc * 8 + tig]);
                            XB[nn][kc][1] = tf32_of(wr[kc * 8 + tig + 4]);
                        }
                    }
                    float acc[6][4];
#pragma unroll
                    for (int nn = 0; nn < 6; ++nn)
                        acc[nn][0] = acc[nn][1] = acc[nn][2] = acc[nn][3] = 0.0f;
#pragma unroll
                    for (int kc = 0; kc < 4; ++kc) {
                        const u32 h0 = UH[kc * 4 + 0], h1 = UH[kc * 4 + 1];
                        const u32 h2 = UH[kc * 4 + 2], h3 = UH[kc * 4 + 3];
                        const u32 o0 = UL[kc * 4 + 0], o1 = UL[kc * 4 + 1];
                        const u32 o2 = UL[kc * 4 + 2], o3 = UL[kc * 4 + 3];
#pragma unroll
                        for (int nn = 0; nn < 6; ++nn) {
                            mma_tf32(acc[nn][0], acc[nn][1], acc[nn][2], acc[nn][3],
                                     h0, h1, h2, h3, XB[nn][kc][0], XB[nn][kc][1]);
                            mma_tf32(acc[nn][0], acc[nn][1], acc[nn][2], acc[nn][3],
                                     o0, o1, o2, o3, XB[nn][kc][0], XB[nn][kc][1]);
                        }
                    }
#pragma unroll
                    for (int nn = 0; nn < 6; ++nn) {
                        const int nt = half * 6 + nn;
                        const u32 cb = (u32)(nt * 8 + 2 * tig) * 4u;
                        // row g  -> step g   ; row g+8 -> step g+8 (+8*400 B)
                        sts64(base + cb, pack2(acc[nn][0], acc[nn][1]));
                        sts64(base + 3200u + cb, pack2(acc[nn][2], acc[nn][3]));
                    }
                }
            }
            bar_all();
        }
    }
}

extern "C" void kernel_launch(void* const* d_in, const int* in_sizes, int n_in,
                              void* d_out, int out_size) {
    const float* x        = (const float*)d_in[0];
    const float* proj1_w  = (const float*)d_in[1];
    const float* proj1_b  = (const float*)d_in[2];
    const float* gru1_wih = (const float*)d_in[3];
    const float* gru1_whh = (const float*)d_in[4];
    const float* gru1_bih = (const float*)d_in[5];
    const float* gru1_bhh = (const float*)d_in[6];
    const float* proj2_w  = (const float*)d_in[7];
    const float* proj2_b  = (const float*)d_in[8];
    const float* gru2_wih = (const float*)d_in[9];
    const float* gru2_whh = (const float*)d_in[10];
    const float* gru2_bih = (const float*)d_in[11];
    const float* gru2_bhh = (const float*)d_in[12];
    const float* clf_w    = (const float*)d_in[13];
    const float* clf_b    = (const float*)d_in[14];
    float* out = (float*)d_out;

    float *pa, *pc, *ph1;
    cudaGetSymbolAddress((void**)&pa, g_a);
    cudaGetSymbolAddress((void**)&pc, g_c);
    cudaGetSymbolAddress((void**)&ph1, g_h1);

    cudaFuncSetAttribute(gru_fused_kernel<0>,
                         cudaFuncAttributeMaxDynamicSharedMemorySize, SMEM_TOT);
    cudaFuncSetAttribute(gru_fused_kernel<1>,
                         cudaFuncAttributeMaxDynamicSharedMemorySize, SMEM_TOT);

    // Stage 1
    pre_kernel<16><<<128, 256>>>(x, proj1_w, proj1_b, pa, pc);
    gru_fused_kernel<0><<<256, 256, SMEM_TOT>>>(pa, pc, gru1_wih, gru1_whh,
                                                gru1_bih, gru1_bhh,
                                                nullptr, nullptr, ph1);
    // Stage 2
    pre_kernel<32><<<128, 256>>>(ph1, proj2_w, proj2_b, pa, pc);
    gru_fused_kernel<1><<<256, 256, SMEM_TOT>>>(pa, pc, gru2_wih, gru2_whh,
                                                gru2_bih, gru2_bhh,
                                                clf_w, clf_b, out);
}